// round 8
// baseline (speedup 1.0000x reference)
#include <cuda_runtime.h>

#define IMG_H 480
#define IMG_W 640
#define NPIX (IMG_H * IMG_W)
#define NB 16
#define NTHR 128
#define BLK_X 1200                        // 1200 * 128 threads * 2 px = 307200 = NPIX
#define NBLOCKS (BLK_X * 2)

__device__ double       g_sum;
__device__ unsigned int g_count;

// Per-pixel: project (pre-scaled), clamp, bilinear-gather (border), |d - s|.
// uu/vv are already scaled by W/(W-1), H/(H-1) via the folded matrices.
__device__ __forceinline__ float px_loss(const float* __restrict__ plane,
                                         float uu, float vv, float dd) {
    float denom = fmaxf(dd, 0.0f) + 1e-12f;
    float r;
    asm("rcp.approx.ftz.f32 %0, %1;" : "=f"(r) : "f"(denom));

    float x = fmaf(uu, r, -0.5f);
    float y = fmaf(vv, r, -0.5f);
    x = fminf(fmaxf(x, 0.0f), (float)(IMG_W - 1));
    y = fminf(fmaxf(y, 0.0f), (float)(IMG_H - 1));

    int   x0 = (int)x;                 // x >= 0 -> trunc == floor
    int   y0 = (int)y;
    float wx = x - (float)x0;
    float wy = y - (float)y0;
    int   x1 = min(x0 + 1, IMG_W - 1);
    int   y1 = min(y0 + 1, IMG_H - 1);

    const float* r0 = plane + y0 * IMG_W;
    const float* r1 = plane + y1 * IMG_W;
    float v00 = __ldg(r0 + x0);
    float v01 = __ldg(r0 + x1);
    float v10 = __ldg(r1 + x0);
    float v11 = __ldg(r1 + x1);

    float top = fmaf(wx, v01 - v00, v00);
    float bot = fmaf(wx, v11 - v10, v10);
    float s   = fmaf(wy, bot - top, top);
    return fabsf(dd - s);
}

// ---------------------------------------------------------------------------
// 2 pixels per thread, 12 blocks/SM residency. blockIdx.y = direction.
// ---------------------------------------------------------------------------
__global__ __launch_bounds__(NTHR, 12)
void pdsl_fused(const float* __restrict__ depth0,
                const float* __restrict__ depth1,
                const float* __restrict__ R0, const float* __restrict__ t0,
                const float* __restrict__ R1, const float* __restrict__ t1,
                const float* __restrict__ Kp,
                float* __restrict__ out) {
    __shared__ float sMC[NB * 12];       // this direction only: P[9], c[3] per batch
    const int tid = threadIdx.x;
    const int dir = blockIdx.y;

    // ---- fold transforms (threads 0..15, one batch each) ----
    if (tid < NB) {
        int b = tid;

        float K[9];
#pragma unroll
        for (int i = 0; i < 9; i++) K[i] = Kp[i];

        // analytic 3x3 inverse of K
        float det = K[0] * (K[4] * K[8] - K[5] * K[7])
                  - K[1] * (K[3] * K[8] - K[5] * K[6])
                  + K[2] * (K[3] * K[7] - K[4] * K[6]);
        float id = 1.0f / det;
        float Ki[9];
        Ki[0] = (K[4] * K[8] - K[5] * K[7]) * id;
        Ki[1] = (K[2] * K[7] - K[1] * K[8]) * id;
        Ki[2] = (K[1] * K[5] - K[2] * K[4]) * id;
        Ki[3] = (K[5] * K[6] - K[3] * K[8]) * id;
        Ki[4] = (K[0] * K[8] - K[2] * K[6]) * id;
        Ki[5] = (K[2] * K[3] - K[0] * K[5]) * id;
        Ki[6] = (K[3] * K[7] - K[4] * K[6]) * id;
        Ki[7] = (K[1] * K[6] - K[0] * K[7]) * id;
        Ki[8] = (K[0] * K[4] - K[1] * K[3]) * id;

        const float* Rs = (dir == 0 ? R0 : R1) + b * 9;
        const float* Rd = (dir == 0 ? R1 : R0) + b * 9;
        const float* ts = (dir == 0 ? t0 : t1) + b * 3;
        const float* td = (dir == 0 ? t1 : t0) + b * 3;

        float A[9];  // Rd * Rs^T
#pragma unroll
        for (int i = 0; i < 3; i++)
#pragma unroll
            for (int j = 0; j < 3; j++)
                A[i * 3 + j] = Rd[i * 3 + 0] * Rs[j * 3 + 0]
                             + Rd[i * 3 + 1] * Rs[j * 3 + 1]
                             + Rd[i * 3 + 2] * Rs[j * 3 + 2];
        float M[9];  // K * A
#pragma unroll
        for (int i = 0; i < 3; i++)
#pragma unroll
            for (int j = 0; j < 3; j++)
                M[i * 3 + j] = K[i * 3 + 0] * A[0 * 3 + j]
                             + K[i * 3 + 1] * A[1 * 3 + j]
                             + K[i * 3 + 2] * A[2 * 3 + j];

        // row scales fold the grid-sample normalization round trip:
        //   x = (u/d)*W/(W-1) - 0.5  -> pre-scale row0 by W/(W-1), row1 by H/(H-1)
        const float rs[3] = { (float)IMG_W / (float)(IMG_W - 1),
                              (float)IMG_H / (float)(IMG_H - 1), 1.0f };

        float* mc = &sMC[b * 12];
#pragma unroll
        for (int i = 0; i < 3; i++)          // P = rs[i] * (M * Ki)
#pragma unroll
            for (int j = 0; j < 3; j++)
                mc[i * 3 + j] = rs[i] * (M[i * 3 + 0] * Ki[0 * 3 + j]
                                       + M[i * 3 + 1] * Ki[1 * 3 + j]
                                       + M[i * 3 + 2] * Ki[2 * 3 + j]);
#pragma unroll
        for (int i = 0; i < 3; i++) {        // c = rs[i] * (K*td - M*ts)
            float Ktd = K[i * 3 + 0] * td[0] + K[i * 3 + 1] * td[1] + K[i * 3 + 2] * td[2];
            mc[9 + i] = rs[i] * (Ktd - (M[i * 3 + 0] * ts[0]
                                      + M[i * 3 + 1] * ts[1]
                                      + M[i * 3 + 2] * ts[2]));
        }
    }
    __syncthreads();

    const float* __restrict__ dsrc = dir ? depth1 : depth0;
    const float* __restrict__ ddst = dir ? depth0 : depth1;

    // ---- exactly one 2-pixel tile per thread ----
    const int tile = blockIdx.x * NTHR + tid;        // 0..153599 per dir
    const int p    = tile * 2;                       // 640 % 2 == 0: never crosses rows
    const int vy   = p / IMG_W;
    const int ux   = p - vy * IMG_W;
    const float uf = (float)ux;
    const float vf = (float)vy;

    float acc = 0.0f;
#pragma unroll 2
    for (int b = 0; b < NB; b++) {
        const float* mc = &sMC[b * 12];
        float P00 = mc[0], P01 = mc[1], P02 = mc[2];
        float P10 = mc[3], P11 = mc[4], P12 = mc[5];
        float P20 = mc[6], P21 = mc[7], P22 = mc[8];
        float c0  = mc[9], c1  = mc[10], c2 = mc[11];

        // P * (u, v, 1); advances by P.col0 per pixel along the row
        float bx = fmaf(P00, uf, fmaf(P01, vf, P02));
        float by = fmaf(P10, uf, fmaf(P11, vf, P12));
        float bd = fmaf(P20, uf, fmaf(P21, vf, P22));

        float2 d2 = *(const float2*)(dsrc + b * NPIX + p);
        const float* plane = ddst + b * NPIX;

        acc += px_loss(plane, fmaf(d2.x, bx, c0), fmaf(d2.x, by, c1), fmaf(d2.x, bd, c2));
        bx += P00; by += P10; bd += P20;
        acc += px_loss(plane, fmaf(d2.y, bx, c0), fmaf(d2.y, by, c1), fmaf(d2.y, bd, c2));
    }

    // ---- block reduction ----
#pragma unroll
    for (int off = 16; off > 0; off >>= 1)
        acc += __shfl_down_sync(0xffffffffu, acc, off);

    __shared__ float warpsum[NTHR / 32];
    if ((tid & 31) == 0) warpsum[tid >> 5] = acc;
    __syncthreads();
    if (tid < 32) {
        float s = (tid < NTHR / 32) ? warpsum[tid] : 0.0f;
#pragma unroll
        for (int off = 2; off > 0; off >>= 1)
            s += __shfl_down_sync(0xffffffffu, s, off);
        if (tid == 0) {
            atomicAdd(&g_sum, (double)s);
            __threadfence();
            unsigned prev = atomicAdd(&g_count, 1u);
            if (prev == NBLOCKS - 1) {
                double total = atomicAdd(&g_sum, 0.0);
                out[0] = (float)(total * (1.0 / (double)((long long)NB * NPIX)));
                // reset for next graph replay (deterministic re-execution)
                g_sum   = 0.0;
                g_count = 0u;
                __threadfence();
            }
        }
    }
}

// ---------------------------------------------------------------------------
extern "C" void kernel_launch(void* const* d_in, const int* in_sizes, int n_in,
                              void* d_out, int out_size) {
    const float* depth0 = (const float*)d_in[0];
    const float* depth1 = (const float*)d_in[1];
    const float* R0     = (const float*)d_in[2];
    const float* t0     = (const float*)d_in[3];
    const float* R1     = (const float*)d_in[4];
    const float* t1     = (const float*)d_in[5];
    const float* K      = (const float*)d_in[6];

    dim3 grid(BLK_X, 2);
    pdsl_fused<<<grid, NTHR>>>(depth0, depth1, R0, t0, R1, t1, K, (float*)d_out);
}

// round 9
// speedup vs baseline: 1.0720x; 1.0720x over previous
#include <cuda_runtime.h>

#define IMG_H 480
#define IMG_W 640
#define NPIX (IMG_H * IMG_W)
#define NB 16
#define NTHR 128
#define BLK_X 600                         // 600 * 128 threads * 4 px = 307200 = NPIX
#define NBLOCKS (BLK_X * 2)

__device__ double       g_sum;
__device__ unsigned int g_count;

// ---------------------------------------------------------------------------
// 4 pixels per thread; batch loop phased (coords -> 16 batched taps -> math)
// to maximize memory-level parallelism. blockIdx.y = direction.
// ---------------------------------------------------------------------------
__global__ __launch_bounds__(NTHR)
void pdsl_fused(const float* __restrict__ depth0,
                const float* __restrict__ depth1,
                const float* __restrict__ R0, const float* __restrict__ t0,
                const float* __restrict__ R1, const float* __restrict__ t1,
                const float* __restrict__ Kp,
                float* __restrict__ out) {
    __shared__ float sMC[NB * 12];       // this direction only: P[9], c[3] per batch
    const int tid = threadIdx.x;
    const int dir = blockIdx.y;

    // ---- fold transforms (threads 0..15, one batch each) ----
    if (tid < NB) {
        int b = tid;

        float K[9];
#pragma unroll
        for (int i = 0; i < 9; i++) K[i] = Kp[i];

        // analytic 3x3 inverse of K
        float det = K[0] * (K[4] * K[8] - K[5] * K[7])
                  - K[1] * (K[3] * K[8] - K[5] * K[6])
                  + K[2] * (K[3] * K[7] - K[4] * K[6]);
        float id = 1.0f / det;
        float Ki[9];
        Ki[0] = (K[4] * K[8] - K[5] * K[7]) * id;
        Ki[1] = (K[2] * K[7] - K[1] * K[8]) * id;
        Ki[2] = (K[1] * K[5] - K[2] * K[4]) * id;
        Ki[3] = (K[5] * K[6] - K[3] * K[8]) * id;
        Ki[4] = (K[0] * K[8] - K[2] * K[6]) * id;
        Ki[5] = (K[2] * K[3] - K[0] * K[5]) * id;
        Ki[6] = (K[3] * K[7] - K[4] * K[6]) * id;
        Ki[7] = (K[1] * K[6] - K[0] * K[7]) * id;
        Ki[8] = (K[0] * K[4] - K[1] * K[3]) * id;

        const float* Rs = (dir == 0 ? R0 : R1) + b * 9;
        const float* Rd = (dir == 0 ? R1 : R0) + b * 9;
        const float* ts = (dir == 0 ? t0 : t1) + b * 3;
        const float* td = (dir == 0 ? t1 : t0) + b * 3;

        float A[9];  // Rd * Rs^T
#pragma unroll
        for (int i = 0; i < 3; i++)
#pragma unroll
            for (int j = 0; j < 3; j++)
                A[i * 3 + j] = Rd[i * 3 + 0] * Rs[j * 3 + 0]
                             + Rd[i * 3 + 1] * Rs[j * 3 + 1]
                             + Rd[i * 3 + 2] * Rs[j * 3 + 2];
        float M[9];  // K * A
#pragma unroll
        for (int i = 0; i < 3; i++)
#pragma unroll
            for (int j = 0; j < 3; j++)
                M[i * 3 + j] = K[i * 3 + 0] * A[0 * 3 + j]
                             + K[i * 3 + 1] * A[1 * 3 + j]
                             + K[i * 3 + 2] * A[2 * 3 + j];

        // fold grid-sample normalization: x = (u/d)*W/(W-1) - 0.5
        const float rs[3] = { (float)IMG_W / (float)(IMG_W - 1),
                              (float)IMG_H / (float)(IMG_H - 1), 1.0f };

        float* mc = &sMC[b * 12];
#pragma unroll
        for (int i = 0; i < 3; i++)          // P = rs[i] * (M * Ki)
#pragma unroll
            for (int j = 0; j < 3; j++)
                mc[i * 3 + j] = rs[i] * (M[i * 3 + 0] * Ki[0 * 3 + j]
                                       + M[i * 3 + 1] * Ki[1 * 3 + j]
                                       + M[i * 3 + 2] * Ki[2 * 3 + j]);
#pragma unroll
        for (int i = 0; i < 3; i++) {        // c = rs[i] * (K*td - M*ts)
            float Ktd = K[i * 3 + 0] * td[0] + K[i * 3 + 1] * td[1] + K[i * 3 + 2] * td[2];
            mc[9 + i] = rs[i] * (Ktd - (M[i * 3 + 0] * ts[0]
                                      + M[i * 3 + 1] * ts[1]
                                      + M[i * 3 + 2] * ts[2]));
        }
    }
    __syncthreads();

    const float* __restrict__ dsrc = dir ? depth1 : depth0;
    const float* __restrict__ ddst = dir ? depth0 : depth1;

    // ---- exactly one 4-pixel tile per thread ----
    const int tile = blockIdx.x * NTHR + tid;        // 0..76799
    const int p    = tile * 4;                       // 640 % 4 == 0: never crosses rows
    const int vy   = p / IMG_W;
    const int ux   = p - vy * IMG_W;
    const float uf = (float)ux;
    const float vf = (float)vy;

    float acc = 0.0f;

#pragma unroll 2
    for (int b = 0; b < NB; b++) {
        const float* mc = &sMC[b * 12];
        const float P00 = mc[0], P01 = mc[1], P02 = mc[2];
        const float P10 = mc[3], P11 = mc[4], P12 = mc[5];
        const float P20 = mc[6], P21 = mc[7], P22 = mc[8];
        const float c0  = mc[9], c1  = mc[10], c2 = mc[11];

        float4 d4 = *(const float4*)(dsrc + b * NPIX + p);
        const float dv[4] = { d4.x, d4.y, d4.z, d4.w };
        const float* __restrict__ plane = ddst + b * NPIX;

        // ---- Phase A: all 4 pixels' coordinates ----
        float bx0 = fmaf(P00, uf, fmaf(P01, vf, P02));
        float by0 = fmaf(P10, uf, fmaf(P11, vf, P12));
        float bd0 = fmaf(P20, uf, fmaf(P21, vf, P22));

        float wx[4], wy[4], dd[4];
        int   i00[4], i01[4], i10[4], i11[4];
#pragma unroll
        for (int j = 0; j < 4; j++) {
            float bx = fmaf(P00, (float)j, bx0);
            float by = fmaf(P10, (float)j, by0);
            float bd = fmaf(P20, (float)j, bd0);
            float uu = fmaf(dv[j], bx, c0);
            float vv = fmaf(dv[j], by, c1);
            float d  = fmaf(dv[j], bd, c2);
            dd[j] = d;

            float denom = fmaxf(d, 0.0f) + 1e-12f;
            float r;
            asm("rcp.approx.ftz.f32 %0, %1;" : "=f"(r) : "f"(denom));

            float x = fmaf(uu, r, -0.5f);
            float y = fmaf(vv, r, -0.5f);
            x = fminf(fmaxf(x, 0.0f), (float)(IMG_W - 1));
            y = fminf(fmaxf(y, 0.0f), (float)(IMG_H - 1));

            int x0 = (int)x;                 // x >= 0 -> trunc == floor
            int y0 = (int)y;
            wx[j] = x - (float)x0;
            wy[j] = y - (float)y0;
            int x1 = min(x0 + 1, IMG_W - 1);
            int y1 = min(y0 + 1, IMG_H - 1);
            int r0 = y0 * IMG_W;
            int r1 = y1 * IMG_W;
            i00[j] = r0 + x0;  i01[j] = r0 + x1;
            i10[j] = r1 + x0;  i11[j] = r1 + x1;
        }

        // ---- Phase B: issue all 16 taps (independent -> deep MLP) ----
        float v00[4], v01[4], v10[4], v11[4];
#pragma unroll
        for (int j = 0; j < 4; j++) {
            v00[j] = __ldg(plane + i00[j]);
            v01[j] = __ldg(plane + i01[j]);
            v10[j] = __ldg(plane + i10[j]);
            v11[j] = __ldg(plane + i11[j]);
        }

        // ---- Phase C: bilinear + |diff| ----
#pragma unroll
        for (int j = 0; j < 4; j++) {
            float top = fmaf(wx[j], v01[j] - v00[j], v00[j]);
            float bot = fmaf(wx[j], v11[j] - v10[j], v10[j]);
            float s   = fmaf(wy[j], bot - top, top);
            acc += fabsf(dd[j] - s);
        }
    }

    // ---- block reduction ----
#pragma unroll
    for (int off = 16; off > 0; off >>= 1)
        acc += __shfl_down_sync(0xffffffffu, acc, off);

    __shared__ float warpsum[NTHR / 32];
    if ((tid & 31) == 0) warpsum[tid >> 5] = acc;
    __syncthreads();
    if (tid < 32) {
        float s = (tid < NTHR / 32) ? warpsum[tid] : 0.0f;
#pragma unroll
        for (int off = 2; off > 0; off >>= 1)
            s += __shfl_down_sync(0xffffffffu, s, off);
        if (tid == 0) {
            atomicAdd(&g_sum, (double)s);
            __threadfence();
            unsigned prev = atomicAdd(&g_count, 1u);
            if (prev == NBLOCKS - 1) {
                double total = atomicAdd(&g_sum, 0.0);
                out[0] = (float)(total * (1.0 / (double)((long long)NB * NPIX)));
                // reset for next graph replay (deterministic re-execution)
                g_sum   = 0.0;
                g_count = 0u;
                __threadfence();
            }
        }
    }
}

// ---------------------------------------------------------------------------
extern "C" void kernel_launch(void* const* d_in, const int* in_sizes, int n_in,
                              void* d_out, int out_size) {
    const float* depth0 = (const float*)d_in[0];
    const float* depth1 = (const float*)d_in[1];
    const float* R0     = (const float*)d_in[2];
    const float* t0     = (const float*)d_in[3];
    const float* R1     = (const float*)d_in[4];
    const float* t1     = (const float*)d_in[5];
    const float* K      = (const float*)d_in[6];

    dim3 grid(BLK_X, 2);
    pdsl_fused<<<grid, NTHR>>>(depth0, depth1, R0, t0, R1, t1, K, (float*)d_out);
}

// round 11
// speedup vs baseline: 1.1332x; 1.0571x over previous
#include <cuda_runtime.h>

#define IMG_H 480
#define IMG_W 640
#define NPIX (IMG_H * IMG_W)
#define NB 16
#define NTHR 128
#define BLK_X 600                         // 600 * 128 threads * 4 px = 307200 = NPIX
#define NBLOCKS (BLK_X * 2)

__device__ double       g_sum;
__device__ unsigned int g_count;

// ---------------------------------------------------------------------------
// 4 pixels per thread. Fast path for d<=0 (reference: denom=1e-12 -> coords
// saturate by sign -> corner pixel, zero bilinear weights). blockIdx.y = dir.
// ---------------------------------------------------------------------------
__global__ __launch_bounds__(NTHR)
void pdsl_fused(const float* __restrict__ depth0,
                const float* __restrict__ depth1,
                const float* __restrict__ R0, const float* __restrict__ t0,
                const float* __restrict__ R1, const float* __restrict__ t1,
                const float* __restrict__ Kp,
                float* __restrict__ out) {
    __shared__ float sMC[NB * 12];       // per batch: P[9] (pre-scaled), c[3]
    __shared__ float sCorner[NB * 4];    // per batch: plane corners [y>0?][x>0?]
    const int tid = threadIdx.x;
    const int dir = blockIdx.y;

    const float* __restrict__ dsrc = dir ? depth1 : depth0;
    const float* __restrict__ ddst = dir ? depth0 : depth1;

    // ---- fold transforms (threads 0..15, one batch each) ----
    if (tid < NB) {
        int b = tid;

        float K[9];
#pragma unroll
        for (int i = 0; i < 9; i++) K[i] = Kp[i];

        // analytic 3x3 inverse of K
        float det = K[0] * (K[4] * K[8] - K[5] * K[7])
                  - K[1] * (K[3] * K[8] - K[5] * K[6])
                  + K[2] * (K[3] * K[7] - K[4] * K[6]);
        float id = 1.0f / det;
        float Ki[9];
        Ki[0] = (K[4] * K[8] - K[5] * K[7]) * id;
        Ki[1] = (K[2] * K[7] - K[1] * K[8]) * id;
        Ki[2] = (K[1] * K[5] - K[2] * K[4]) * id;
        Ki[3] = (K[5] * K[6] - K[3] * K[8]) * id;
        Ki[4] = (K[0] * K[8] - K[2] * K[6]) * id;
        Ki[5] = (K[2] * K[3] - K[0] * K[5]) * id;
        Ki[6] = (K[3] * K[7] - K[4] * K[6]) * id;
        Ki[7] = (K[1] * K[6] - K[0] * K[7]) * id;
        Ki[8] = (K[0] * K[4] - K[1] * K[3]) * id;

        const float* Rs = (dir == 0 ? R0 : R1) + b * 9;
        const float* Rd = (dir == 0 ? R1 : R0) + b * 9;
        const float* ts = (dir == 0 ? t0 : t1) + b * 3;
        const float* td = (dir == 0 ? t1 : t0) + b * 3;

        float A[9];  // Rd * Rs^T
#pragma unroll
        for (int i = 0; i < 3; i++)
#pragma unroll
            for (int j = 0; j < 3; j++)
                A[i * 3 + j] = Rd[i * 3 + 0] * Rs[j * 3 + 0]
                             + Rd[i * 3 + 1] * Rs[j * 3 + 1]
                             + Rd[i * 3 + 2] * Rs[j * 3 + 2];
        float M[9];  // K * A
#pragma unroll
        for (int i = 0; i < 3; i++)
#pragma unroll
            for (int j = 0; j < 3; j++)
                M[i * 3 + j] = K[i * 3 + 0] * A[0 * 3 + j]
                             + K[i * 3 + 1] * A[1 * 3 + j]
                             + K[i * 3 + 2] * A[2 * 3 + j];

        // fold grid-sample normalization: x = (u/d)*W/(W-1) - 0.5
        const float rs[3] = { (float)IMG_W / (float)(IMG_W - 1),
                              (float)IMG_H / (float)(IMG_H - 1), 1.0f };

        float* mc = &sMC[b * 12];
#pragma unroll
        for (int i = 0; i < 3; i++)          // P = rs[i] * (M * Ki)
#pragma unroll
            for (int j = 0; j < 3; j++)
                mc[i * 3 + j] = rs[i] * (M[i * 3 + 0] * Ki[0 * 3 + j]
                                       + M[i * 3 + 1] * Ki[1 * 3 + j]
                                       + M[i * 3 + 2] * Ki[2 * 3 + j]);
#pragma unroll
        for (int i = 0; i < 3; i++) {        // c = rs[i] * (K*td - M*ts)
            float Ktd = K[i * 3 + 0] * td[0] + K[i * 3 + 1] * td[1] + K[i * 3 + 2] * td[2];
            mc[9 + i] = rs[i] * (Ktd - (M[i * 3 + 0] * ts[0]
                                      + M[i * 3 + 1] * ts[1]
                                      + M[i * 3 + 2] * ts[2]));
        }
    }
    // corner table: idx bit0 = (uu>0), bit1 = (vv>0)
    if (tid < NB * 4) {
        int b = tid >> 2;
        int k = tid & 3;
        int cy = (k & 2) ? (IMG_H - 1) : 0;
        int cx = (k & 1) ? (IMG_W - 1) : 0;
        sCorner[tid] = ddst[b * NPIX + cy * IMG_W + cx];
    }
    __syncthreads();

    // ---- exactly one 4-pixel tile per thread ----
    const int tile = blockIdx.x * NTHR + tid;        // 0..76799
    const int p    = tile * 4;                       // 640 % 4 == 0: never crosses rows
    const int vy   = p / IMG_W;
    const int ux   = p - vy * IMG_W;
    const float uf = (float)ux;
    const float vf = (float)vy;

    float acc = 0.0f;

#pragma unroll 2
    for (int b = 0; b < NB; b++) {
        const float* mc = &sMC[b * 12];
        const float P00 = mc[0], P01 = mc[1], P02 = mc[2];
        const float P10 = mc[3], P11 = mc[4], P12 = mc[5];
        const float P20 = mc[6], P21 = mc[7], P22 = mc[8];
        const float c0  = mc[9], c1  = mc[10], c2 = mc[11];

        float4 d4 = *(const float4*)(dsrc + b * NPIX + p);
        const float dv[4] = { d4.x, d4.y, d4.z, d4.w };
        const float* __restrict__ plane = ddst + b * NPIX;
        const float* __restrict__ corner = &sCorner[b * 4];

        float bx = fmaf(P00, uf, fmaf(P01, vf, P02));
        float by = fmaf(P10, uf, fmaf(P11, vf, P12));
        float bd = fmaf(P20, uf, fmaf(P21, vf, P22));

#pragma unroll
        for (int j = 0; j < 4; j++) {
            float uu = fmaf(dv[j], bx, c0);
            float vv = fmaf(dv[j], by, c1);
            float d  = fmaf(dv[j], bd, c2);

            float s;
            if (d <= 0.0f) {
                // denom = 1e-12 -> coords saturate by sign -> exact corner,
                // wx = wy = 0 -> bilinear == corner value
                int ci = ((vv > 0.0f) ? 2 : 0) | ((uu > 0.0f) ? 1 : 0);
                s = corner[ci];
            } else {
                float denom = d + 1e-12f;
                float r;
                asm("rcp.approx.ftz.f32 %0, %1;" : "=f"(r) : "f"(denom));

                float x = fmaf(uu, r, -0.5f);
                float y = fmaf(vv, r, -0.5f);
                x = fminf(fmaxf(x, 0.0f), (float)(IMG_W - 1));
                y = fminf(fmaxf(y, 0.0f), (float)(IMG_H - 1));

                int   x0 = (int)x;             // x >= 0 -> trunc == floor
                int   y0 = (int)y;
                float wx = x - (float)x0;
                float wy = y - (float)y0;
                int   x1 = min(x0 + 1, IMG_W - 1);
                int   y1 = min(y0 + 1, IMG_H - 1);

                const float* r0 = plane + y0 * IMG_W;
                const float* r1 = plane + y1 * IMG_W;
                float v00 = __ldg(r0 + x0);
                float v01 = __ldg(r0 + x1);
                float v10 = __ldg(r1 + x0);
                float v11 = __ldg(r1 + x1);

                float top = fmaf(wx, v01 - v00, v00);
                float bot = fmaf(wx, v11 - v10, v10);
                s = fmaf(wy, bot - top, top);
            }
            acc += fabsf(d - s);

            bx += P00; by += P10; bd += P20;
        }
    }

    // ---- block reduction ----
#pragma unroll
    for (int off = 16; off > 0; off >>= 1)
        acc += __shfl_down_sync(0xffffffffu, acc, off);

    __shared__ float warpsum[NTHR / 32];
    if ((tid & 31) == 0) warpsum[tid >> 5] = acc;
    __syncthreads();
    if (tid < 32) {
        float s = (tid < NTHR / 32) ? warpsum[tid] : 0.0f;
#pragma unroll
        for (int off = 2; off > 0; off >>= 1)
            s += __shfl_down_sync(0xffffffffu, s, off);
        if (tid == 0) {
            atomicAdd(&g_sum, (double)s);
            __threadfence();
            unsigned prev = atomicAdd(&g_count, 1u);
            if (prev == NBLOCKS - 1) {
                double total = atomicAdd(&g_sum, 0.0);
                out[0] = (float)(total * (1.0 / (double)((long long)NB * NPIX)));
                // reset for next graph replay (deterministic re-execution)
                g_sum   = 0.0;
                g_count = 0u;
                __threadfence();
            }
        }
    }
}

// ---------------------------------------------------------------------------
extern "C" void kernel_launch(void* const* d_in, const int* in_sizes, int n_in,
                              void* d_out, int out_size) {
    const float* depth0 = (const float*)d_in[0];
    const float* depth1 = (const float*)d_in[1];
    const float* R0     = (const float*)d_in[2];
    const float* t0     = (const float*)d_in[3];
    const float* R1     = (const float*)d_in[4];
    const float* t1     = (const float*)d_in[5];
    const float* K      = (const float*)d_in[6];

    dim3 grid(BLK_X, 2);
    pdsl_fused<<<grid, NTHR>>>(depth0, depth1, R0, t0, R1, t1, K, (float*)d_out);
}